// round 6
// baseline (speedup 1.0000x reference)
#include <cuda_runtime.h>
#include <cstdint>

// input f32 [4,64,512,512], gathered f32 [2048,64,16,16], indices (b,hb,wb)
// int32 or int64 (detected on device). stride==kernel==16 -> 4096 disjoint
// 16x16 slots; duplicates handled via per-slot linked lists. Main pass:
// out = in + sum(patches in slot), 640MB total traffic, 256-bit streaming
// accesses. Setup fused into a single 16-block kernel with a device-wide
// ticket barrier (monotonic counter: no reset needed, replay-safe).

#define BB 4
#define CC 64
#define HH 512
#define WW 512
#define NN 2048
#define NSLOTS 4096   // BB * 32 * 32

__device__ int g_head[NSLOTS];
__device__ int g_next[NN];
__device__ unsigned g_bar;   // zero-initialized at module load; monotonic

// 16 blocks x 256 threads = 4096 threads.
// Phase 1: every thread inits one head entry.
// Barrier: ticket-based (monotonic across launches, so graph replays work).
// Phase 2: per-block dtype detection + list build (first 2048 threads).
__global__ void __launch_bounds__(256) setup_kernel(const void* __restrict__ idx_raw) {
    __shared__ unsigned s_ticket;
    __shared__ int s_is64;
    int t = blockIdx.x * 256 + threadIdx.x;   // < 4096

    g_head[t] = -1;
    __threadfence();                           // publish init before arrive

    if (threadIdx.x == 0) {
        s_ticket = atomicAdd(&g_bar, 1u);
        s_is64 = 1;
    }
    __syncthreads();
    if (threadIdx.x == 0) {
        unsigned target = (s_ticket - (s_ticket & 15u)) + 16u;
        while (*(volatile unsigned*)&g_bar < target) { }
    }
    __syncthreads();
    __threadfence();                           // acquire others' inits

    // Dtype detect: first 3072 uint64 words = 24576 bytes (full buffer if
    // int32 = N*3*4 bytes, half if int64). Genuine int64 index values are
    // < 512 so every high word is zero; int32 data read as int64 has the
    // neighboring field in the high word (nonzero somewhere, overwhelming
    // probability over 3072 words).
    const unsigned long long* w = (const unsigned long long*)idx_raw;
    #pragma unroll
    for (int i = threadIdx.x; i < 3072; i += 256)
        if ((w[i] >> 32) != 0ull) s_is64 = 0;   // benign race
    __syncthreads();

    if (t < NN) {
        int b, hb, wb;
        if (s_is64) {
            const long long* idx = (const long long*)idx_raw;
            b  = (int)idx[3 * t + 0];
            hb = (int)idx[3 * t + 1];
            wb = (int)idx[3 * t + 2];
        } else {
            const int* idx = (const int*)idx_raw;
            b  = idx[3 * t + 0];
            hb = idx[3 * t + 1];
            wb = idx[3 * t + 2];
        }
        int slot = (b << 10) | (hb << 5) | wb;
        g_next[t] = atomicExch(&g_head[slot & (NSLOTS - 1)], t);
    }
}

__device__ __forceinline__ void ldg256cs(const float* p, float* v) {
    asm volatile("ld.global.cs.v8.f32 {%0,%1,%2,%3,%4,%5,%6,%7}, [%8];"
                 : "=f"(v[0]), "=f"(v[1]), "=f"(v[2]), "=f"(v[3]),
                   "=f"(v[4]), "=f"(v[5]), "=f"(v[6]), "=f"(v[7])
                 : "l"(p));
}

__device__ __forceinline__ void stg256cs(float* p, const float* v) {
    asm volatile("st.global.cs.v8.f32 [%0], {%1,%2,%3,%4,%5,%6,%7,%8};"
                 :: "l"(p),
                    "f"(v[0]), "f"(v[1]), "f"(v[2]), "f"(v[3]),
                    "f"(v[4]), "f"(v[5]), "f"(v[6]), "f"(v[7])
                 : "memory");
}

// One float8 (32B) per thread. 67,108,864 floats -> 8,388,608 float8
// -> 32768 blocks of 256 threads. All accesses 32B-aligned, 1KB/warp on the
// in/out streams; 64B-contiguous per slot-pair on the gathered stream.
__global__ void __launch_bounds__(256) scatter_main_kernel(
    const float* __restrict__ in,
    const float* __restrict__ g,
    float* __restrict__ out)
{
    unsigned i8 = blockIdx.x * 256u + threadIdx.x;   // < 2^23

    unsigned w8 = i8 & 63u;           // float8 column: w = w8*8
    unsigned h  = (i8 >> 6) & 511u;
    unsigned c  = (i8 >> 15) & 63u;
    unsigned b  = i8 >> 21;

    unsigned slot = (b << 10) | ((h >> 4) << 5) | (w8 >> 1);

    float v[8];
    ldg256cs(in + ((size_t)i8 << 3), v);

    int p = g_head[slot];
    if (p >= 0) {
        // patch offset in float8 units: p*2048 + c*32 + (h&15)*2 + (w8&1)
        unsigned local8 = (c << 5) | ((h & 15u) << 1) | (w8 & 1u);
        do {
            float gv[8];
            ldg256cs(g + (((size_t)((unsigned)p << 11) + local8) << 3), gv);
            #pragma unroll
            for (int j = 0; j < 8; j++) v[j] += gv[j];
            p = g_next[p];
        } while (p >= 0);
    }

    stg256cs(out + ((size_t)i8 << 3), v);
}

extern "C" void kernel_launch(void* const* d_in, const int* in_sizes, int n_in,
                              void* d_out, int out_size) {
    const float* input    = (const float*)d_in[0];
    const float* gathered = (const float*)d_in[1];
    const void*  indices  = d_in[2];
    float* out = (float*)d_out;

    setup_kernel<<<16, 256>>>(indices);

    const unsigned total8 = (unsigned)(BB * CC * HH * WW) / 8u;  // 8,388,608
    scatter_main_kernel<<<total8 / 256, 256>>>(input, gathered, out);
}